// round 9
// baseline (speedup 1.0000x reference)
#include <cuda_runtime.h>
#include <cuda_bf16.h>
#include <cstdint>

#define B_   128
#define T_   1024
#define D_   256
#define HS_  512
#define G4_  2048
#define M1_  (B_ * T_)

#define RCTA 64
#define RTHR 512

// ---------------- device scratch ----------------
__device__ float g_xw[(size_t)M1_ * G4_];            // [(row*T+t)*2048 + pc]
__device__ uint4 g_uf[RCTA * 32 * 4 * 32];           // U frags [cta][kt][nt][lane]
__device__ uint4 g_xfh[(size_t)8192 * 16 * 32];      // x A-frags hi
__device__ uint4 g_xfl[(size_t)8192 * 16 * 32];      // x A-frags lo
__device__ uint4 g_wf[16 * 16 * 16 * 32];            // W B-frags
__device__ uint4 g_hfh[2][8 * 32 * 32];              // h hi A-frags
__device__ uint4 g_hfl[2][8 * 32 * 32];              // h lo A-frags
__device__ unsigned int g_bar_l1[8 * 32];            // tree barrier leaves (128B stride)
__device__ unsigned int g_bar_l2;                    // tree barrier root
__device__ volatile unsigned int g_bar_epoch;

// ---------------- helpers ----------------
__device__ __forceinline__ uint32_t packbf(__nv_bfloat16 a, __nv_bfloat16 b) {
    return ((uint32_t)(*(uint16_t*)&b) << 16) | (uint32_t)(*(uint16_t*)&a);
}
__device__ __forceinline__ void split2(float a, float b, uint32_t& hi, uint32_t& lo) {
    __nv_bfloat16 ah = __float2bfloat16(a), bh = __float2bfloat16(b);
    __nv_bfloat16 al = __float2bfloat16(a - __bfloat162float(ah));
    __nv_bfloat16 bl = __float2bfloat16(b - __bfloat162float(bh));
    hi = packbf(ah, bh);
    lo = packbf(al, bl);
}
__device__ __forceinline__ void mma16816(float* d, const uint4& a, uint32_t b0, uint32_t b1) {
    asm volatile(
        "mma.sync.aligned.m16n8k16.row.col.f32.bf16.bf16.f32 "
        "{%0,%1,%2,%3}, {%4,%5,%6,%7}, {%8,%9}, {%0,%1,%2,%3};"
        : "+f"(d[0]), "+f"(d[1]), "+f"(d[2]), "+f"(d[3])
        : "r"(a.x), "r"(a.y), "r"(a.z), "r"(a.w), "r"(b0), "r"(b1));
}
#define CP_ASYNC16(dst_u32, src_ptr) \
    asm volatile("cp.async.cg.shared.global [%0], [%1], 16;" :: "r"(dst_u32), "l"(src_ptr) : "memory")
#define CP_COMMIT() asm volatile("cp.async.commit_group;" ::: "memory")
#define CP_WAIT(n)  asm volatile("cp.async.wait_group %0;" :: "n"(n) : "memory")

__device__ __forceinline__ float sigmoid_fast(float x) { return 1.f / (1.f + __expf(-x)); }
__device__ __forceinline__ float tanh_fast(float x) { float e = __expf(2.f * x); return 1.f - 2.f / (e + 1.f); }

// orig gate col c = gate*512 + hcol -> pc = (hcol/8)*32 + gate*8 + hcol%8
__device__ __forceinline__ int cperm(int c) {
    int g = c >> 9, hc = c & 511;
    return ((hc >> 3) << 5) + (g << 3) + (hc & 7);
}

// ---------------- init ----------------
__global__ void init_kernel() {
    int i = blockIdx.x * blockDim.x + threadIdx.x;
    if (i == 0) { g_bar_l2 = 0; g_bar_epoch = 0; }
    if (i < 8 * 32) g_bar_l1[i] = 0u;
    if (i < 8 * 32 * 32) {
        g_hfh[0][i] = make_uint4(0, 0, 0, 0);
        g_hfl[0][i] = make_uint4(0, 0, 0, 0);
    }
}

// ---------------- U fragment prep ----------------
__global__ __launch_bounds__(256) void uf_prep(const float* __restrict__ U) {
    int i = blockIdx.x * 256 + threadIdx.x;
    int l = i & 31, nt = (i >> 5) & 3, kt = (i >> 7) & 31, cta = i >> 12;
    int n = nt * 8 + (l >> 2);
    int k0 = kt * 16 + (l & 3) * 2;
    int c = (n >> 3) * 512 + cta * 8 + (n & 7);
    float u00 = U[(size_t)k0 * G4_ + c];
    float u01 = U[(size_t)(k0 + 1) * G4_ + c];
    float u10 = U[(size_t)(k0 + 8) * G4_ + c];
    float u11 = U[(size_t)(k0 + 9) * G4_ + c];
    uint32_t b0h, b0l, b1h, b1l;
    split2(u00, u01, b0h, b0l);
    split2(u10, u11, b1h, b1l);
    g_uf[i] = make_uint4(b0h, b1h, b0l, b1l);
}

// ---------------- x fragment prep ----------------
__global__ __launch_bounds__(256) void split_xf(const float* __restrict__ x) {
    size_t i = (size_t)blockIdx.x * 256 + threadIdx.x;
    int l = (int)(i & 31), kt = (int)((i >> 5) & 15);
    int rg = (int)(i >> 9);
    int row = rg * 16 + (l >> 2);
    int k0 = kt * 16 + (l & 3) * 2;
    uint32_t hi[4], lo[4];
#pragma unroll
    for (int kh = 0; kh < 2; kh++)
#pragma unroll
        for (int rh = 0; rh < 2; rh++) {
            float2 v = *(const float2*)&x[(size_t)(row + 8 * rh) * D_ + k0 + 8 * kh];
            split2(v.x, v.y, hi[kh * 2 + rh], lo[kh * 2 + rh]);
        }
    g_xfh[i] = make_uint4(hi[0], hi[1], hi[2], hi[3]);
    g_xfl[i] = make_uint4(lo[0], lo[1], lo[2], lo[3]);
}

// ---------------- W fragment prep ----------------
__global__ __launch_bounds__(256) void wf_prep(const float* __restrict__ Wm) {
    int i = blockIdx.x * 256 + threadIdx.x;
    int l = i & 31, nc = (i >> 5) & 15, kt = (i >> 9) & 15, cb = i >> 13;
    int n = cb * 128 + nc * 8 + (l >> 2);
    int k0 = kt * 16 + (l & 3) * 2;
    float u00 = Wm[(size_t)k0 * G4_ + n];
    float u01 = Wm[(size_t)(k0 + 1) * G4_ + n];
    float u10 = Wm[(size_t)(k0 + 8) * G4_ + n];
    float u11 = Wm[(size_t)(k0 + 9) * G4_ + n];
    uint32_t b0h, b0l, b1h, b1l;
    split2(u00, u01, b0h, b0l);
    split2(u10, u11, b1h, b1l);
    g_wf[i] = make_uint4(b0h, b1h, b0l, b1l);
}

// ---------------- phase 1: xW = x @ W + bias (mma.sync) ----------------
__global__ __launch_bounds__(256) void xw_mma(const float* __restrict__ bias) {
    const int tid = threadIdx.x;
    const int w = tid >> 5, l = tid & 31;
    const int cb = blockIdx.x, rb = blockIdx.y;
    const int wr = w & 3, wc = w >> 2;

    float acc[2][8][4];
#pragma unroll
    for (int mt = 0; mt < 2; mt++)
#pragma unroll
        for (int nt = 0; nt < 8; nt++)
#pragma unroll
            for (int q = 0; q < 4; q++) acc[mt][nt][q] = 0.f;

#pragma unroll 4
    for (int kt = 0; kt < 16; kt++) {
        uint4 bf[8];
#pragma unroll
        for (int nt = 0; nt < 8; nt++)
            bf[nt] = __ldg(&g_wf[(((cb * 16 + kt) * 16) + wc * 8 + nt) * 32 + l]);
#pragma unroll
        for (int mt = 0; mt < 2; mt++) {
            size_t rg = (size_t)rb * 8 + wr * 2 + mt;
            uint4 ah = __ldg(&g_xfh[(rg * 16 + kt) * 32 + l]);
            uint4 al = __ldg(&g_xfl[(rg * 16 + kt) * 32 + l]);
#pragma unroll
            for (int nt = 0; nt < 8; nt++) {
                mma16816(acc[mt][nt], ah, bf[nt].x, bf[nt].y);
                mma16816(acc[mt][nt], ah, bf[nt].z, bf[nt].w);
                mma16816(acc[mt][nt], al, bf[nt].x, bf[nt].y);
            }
        }
    }

#pragma unroll
    for (int mt = 0; mt < 2; mt++) {
        int r0 = rb * 128 + wr * 32 + mt * 16 + (l >> 2);
#pragma unroll
        for (int nt = 0; nt < 8; nt++) {
            int c = cb * 128 + wc * 64 + nt * 8 + (l & 3) * 2;
            int pc = cperm(c);
            float2 bv = __ldg((const float2*)&bias[c]);
            *(float2*)&g_xw[(size_t)r0 * G4_ + pc] =
                make_float2(acc[mt][nt][0] + bv.x, acc[mt][nt][1] + bv.y);
            *(float2*)&g_xw[(size_t)(r0 + 8) * G4_ + pc] =
                make_float2(acc[mt][nt][2] + bv.x, acc[mt][nt][3] + bv.y);
        }
    }
}

// ---------------- phase 2: persistent mma.sync recurrence ----------------
// 64 CTAs x 512 thr. Warp (mq=w>>2, kq=w&3): M=32 (2 mt), K=64 (8 kt), N=32.
// A frags via cp.async 4-deep smem ring; U frags double-buffered in regs.
#define SPAD  34
#define XPAD  36
#define SRED_ELEMS (4 * 128 * SPAD)
#define XW_ELEMS   (128 * XPAD)
#define ARING_BYTES (4 * 16 * 4 * 512)       // 131072
#define SMEM_BYTES ((SRED_ELEMS + XW_ELEMS) * 4 + ARING_BYTES)   // 219136

__global__ __launch_bounds__(RTHR, 1) void lstm_rec(float* __restrict__ out,
                                                    int write_hc) {
    extern __shared__ float smemf[];
    float* sred = smemf;
    float* xw_s = smemf + SRED_ELEMS;
    char*  aring = (char*)(smemf + SRED_ELEMS + XW_ELEMS);

    const int tid = threadIdx.x;
    const int w = tid >> 5, l = tid & 31;
    const int cta = blockIdx.x;
    const int mq = w >> 2, kq = w & 3;

    const uint32_t aring_u32 = (uint32_t)__cvta_generic_to_shared(aring);
    const uint32_t adst_base = aring_u32 + (uint32_t)w * 2048u + (uint32_t)l * 16u;

    // epilogue role: 2 cells = row_e x hcols {2hp, 2hp+1}
    const int row_e = tid >> 2, hp = tid & 3;
    const int kt_w = cta >> 1;
    const int regb = (cta & 1) * 2 + ((row_e >> 3) & 1);
    const size_t fragidx = ((size_t)(row_e >> 4) * 32 + kt_w) * 32 + (row_e & 7) * 4 + hp;

    const uint4* __restrict__ ub = g_uf + (size_t)cta * 4096;

    float creg[2] = {0.f, 0.f};
    float hlast[2];

#define ISSUE_AITER(Ah_, Al_, i_) do {                                           \
    const int kt_ = kq * 8 + (i_);                                               \
    const uint32_t dst_ = adst_base + (uint32_t)(((i_) & 3) * 32768);            \
    CP_ASYNC16(dst_ +    0u, &(Ah_)[(((mq * 2 + 0) * 32) + kt_) * 32 + l]);      \
    CP_ASYNC16(dst_ +  512u, &(Ah_)[(((mq * 2 + 1) * 32) + kt_) * 32 + l]);      \
    CP_ASYNC16(dst_ + 1024u, &(Al_)[(((mq * 2 + 0) * 32) + kt_) * 32 + l]);      \
    CP_ASYNC16(dst_ + 1536u, &(Al_)[(((mq * 2 + 1) * 32) + kt_) * 32 + l]);      \
    CP_COMMIT();                                                                 \
} while (0)

    for (int t = 0; t < T_; t++) {
        const int p = t & 1;
        const uint4* __restrict__ Ah = g_hfh[p];
        const uint4* __restrict__ Al = g_hfl[p];

        // prologue: issue A iters 0..2 into the ring
        ISSUE_AITER(Ah, Al, 0);
        ISSUE_AITER(Ah, Al, 1);
        ISSUE_AITER(Ah, Al, 2);

        // coalesced xw stage loads (held in regs through mainloop)
        float4 xr[2];
#pragma unroll
        for (int j = 0; j < 2; j++) {
            int rw = w * 8 + j * 4 + (l >> 3);
            xr[j] = __ldcg((const float4*)&g_xw[((size_t)rw * T_ + t) * G4_ + cta * 32 + (l & 7) * 4]);
        }

        // U double-buffer prologue
        uint4 bf[2][4];
#pragma unroll
        for (int nt = 0; nt < 4; nt++)
            bf[0][nt] = __ldg(&ub[((kq * 8) * 4 + nt) * 32 + l]);

        float acc[2][4][4];
#pragma unroll
        for (int mt = 0; mt < 2; mt++)
#pragma unroll
            for (int nt = 0; nt < 4; nt++)
#pragma unroll
                for (int q = 0; q < 4; q++) acc[mt][nt][q] = 0.f;

#pragma unroll
        for (int i = 0; i < 8; i++) {
            const int cur = i & 1;
            if (i < 5) ISSUE_AITER(Ah, Al, i + 3);
            if (i < 7) {
                const int ktn = kq * 8 + i + 1;
#pragma unroll
                for (int nt = 0; nt < 4; nt++)
                    bf[cur ^ 1][nt] = __ldg(&ub[(ktn * 4 + nt) * 32 + l]);
            }
            // wait for iter i's A data (pending groups allowed: min(3, 7-i))
            if (i < 5)      CP_WAIT(3);
            else if (i == 5) CP_WAIT(2);
            else if (i == 6) CP_WAIT(1);
            else             CP_WAIT(0);

            const char* ab = aring + ((i & 3) * 16 + w) * 2048 + l * 16;
            uint4 ah0 = *(const uint4*)(ab +    0);
            uint4 ah1 = *(const uint4*)(ab +  512);
            uint4 al0 = *(const uint4*)(ab + 1024);
            uint4 al1 = *(const uint4*)(ab + 1536);

#pragma unroll
            for (int nt = 0; nt < 4; nt++) {
                mma16816(acc[0][nt], ah0, bf[cur][nt].x, bf[cur][nt].y);
                mma16816(acc[0][nt], ah0, bf[cur][nt].z, bf[cur][nt].w);
                mma16816(acc[0][nt], al0, bf[cur][nt].x, bf[cur][nt].y);
                mma16816(acc[1][nt], ah1, bf[cur][nt].x, bf[cur][nt].y);
                mma16816(acc[1][nt], ah1, bf[cur][nt].z, bf[cur][nt].w);
                mma16816(acc[1][nt], al1, bf[cur][nt].x, bf[cur][nt].y);
            }
        }

        // ---- partials + xw to smem ----
        {
            const int row0 = (l >> 2), n0 = 2 * (l & 3);
#pragma unroll
            for (int mt = 0; mt < 2; mt++)
#pragma unroll
                for (int nt = 0; nt < 4; nt++) {
                    int s = (kq * 128 + (mq * 2 + mt) * 16 + row0) * SPAD + nt * 8 + n0;
                    *(float2*)&sred[s]            = make_float2(acc[mt][nt][0], acc[mt][nt][1]);
                    *(float2*)&sred[s + 8 * SPAD] = make_float2(acc[mt][nt][2], acc[mt][nt][3]);
                }
#pragma unroll
            for (int j = 0; j < 2; j++)
                *(float4*)&xw_s[(w * 8 + j * 4 + (l >> 3)) * XPAD + (l & 7) * 4] = xr[j];
        }
        __syncthreads();

        // ---- reduce + cell update ----
        float2 gsum[4];
#pragma unroll
        for (int g = 0; g < 4; g++) {
            float2 s = *(const float2*)&xw_s[row_e * XPAD + g * 8 + 2 * hp];
#pragma unroll
            for (int q2 = 0; q2 < 4; q2++) {
                float2 v = *(const float2*)&sred[(q2 * 128 + row_e) * SPAD + g * 8 + 2 * hp];
                s.x += v.x; s.y += v.y;
            }
            gsum[g] = s;
        }
        float hnew[2];
#pragma unroll
        for (int q = 0; q < 2; q++) {
            float gi = q ? gsum[0].y : gsum[0].x;
            float gf = q ? gsum[1].y : gsum[1].x;
            float gg = q ? gsum[2].y : gsum[2].x;
            float go = q ? gsum[3].y : gsum[3].x;
            float iv = sigmoid_fast(gi);
            float fv = sigmoid_fast(gf);
            float gv = tanh_fast(gg);
            float ov = sigmoid_fast(go);
            float c = fv * creg[q] + iv * gv;
            creg[q] = c;
            float h = ov * tanh_fast(c);
            hnew[q] = h;
            hlast[q] = h;
        }
        *(float2*)&out[((size_t)row_e * T_ + t) * HS_ + cta * 8 + 2 * hp] =
            make_float2(hnew[0], hnew[1]);

        // h fragment write for next step
        {
            uint32_t hi, lo;
            split2(hnew[0], hnew[1], hi, lo);
            *(uint32_t*)((char*)g_hfh[1 - p] + fragidx * 16 + regb * 4) = hi;
            *(uint32_t*)((char*)g_hfl[1 - p] + fragidx * 16 + regb * 4) = lo;
        }

        // ---- grid barrier: 2-level monotonic atomic tree + epoch spin ----
        if (t < T_ - 1) {
            const unsigned tgt = (unsigned)(t + 1);
            __threadfence();
            __syncthreads();
            if (tid == 0) {
                unsigned old = atomicAdd(&g_bar_l1[(cta & 7) * 32], 1u);
                if (old == 8u * tgt - 1u) {
                    unsigned old2 = atomicAdd(&g_bar_l2, 1u);
                    if (old2 == 8u * tgt - 1u) {
                        __threadfence();
                        g_bar_epoch = tgt;
                    }
                }
                while (g_bar_epoch < tgt) { }
                __threadfence();
            }
            __syncthreads();
        }
    }

    if (write_hc) {
        const size_t OH = (size_t)B_ * T_ * HS_;
        *(float2*)&out[OH + (size_t)row_e * HS_ + cta * 8 + 2 * hp] =
            make_float2(hlast[0], hlast[1]);
        *(float2*)&out[OH + (size_t)B_ * HS_ + (size_t)row_e * HS_ + cta * 8 + 2 * hp] =
            make_float2(creg[0], creg[1]);
    }
#undef ISSUE_AITER
}

// ---------------- launch ----------------
extern "C" void kernel_launch(void* const* d_in, const int* in_sizes, int n_in,
                              void* d_out, int out_size) {
    const float* x    = (const float*)d_in[0];
    const float* Wm   = (const float*)d_in[1];
    const float* U    = (const float*)d_in[2];
    const float* bias = (const float*)d_in[3];
    float* out = (float*)d_out;
    (void)in_sizes; (void)n_in;

    cudaFuncSetAttribute(lstm_rec, cudaFuncAttributeMaxDynamicSharedMemorySize, SMEM_BYTES);

    const long long need_hc = (long long)B_ * T_ * HS_ + 2LL * B_ * HS_;
    int write_hc = ((long long)out_size >= need_hc) ? 1 : 0;

    init_kernel<<<32, 256>>>();
    split_xf<<<16384, 256>>>(x);
    wf_prep<<<512, 256>>>(Wm);
    uf_prep<<<1024, 256>>>(U);
    xw_mma<<<dim3(16, 1024), 256>>>(bias);
    lstm_rec<<<RCTA, RTHR, SMEM_BYTES>>>(out, write_hc);
}

// round 10
// speedup vs baseline: 1.0164x; 1.0164x over previous
#include <cuda_runtime.h>
#include <cuda_bf16.h>
#include <cstdint>

#define B_   128
#define T_   1024
#define D_   256
#define HS_  512
#define G4_  2048
#define M1_  (B_ * T_)

#define RCTA 64
#define RTHR 512

// ---------------- device scratch ----------------
__device__ float g_xw[(size_t)M1_ * G4_];            // [(row*T+t)*2048 + pc]
__device__ uint4 g_uf[RCTA * 32 * 4 * 32];           // U frags [cta][kt][nt][lane]
__device__ uint4 g_xfh[(size_t)8192 * 16 * 32];      // x A-frags hi
__device__ uint4 g_xfl[(size_t)8192 * 16 * 32];      // x A-frags lo
__device__ uint4 g_wf[16 * 16 * 16 * 32];            // W B-frags
__device__ uint4 g_hfh[2][8 * 32 * 32];              // h hi A-frags
__device__ uint4 g_hfl[2][8 * 32 * 32];              // h lo A-frags
__device__ unsigned int g_bar_l1[8 * 32];            // tree barrier leaves (128B stride)
__device__ unsigned int g_bar_l2;                    // tree barrier root
__device__ volatile unsigned int g_bar_epoch;

// ---------------- helpers ----------------
__device__ __forceinline__ uint32_t packbf(__nv_bfloat16 a, __nv_bfloat16 b) {
    return ((uint32_t)(*(uint16_t*)&b) << 16) | (uint32_t)(*(uint16_t*)&a);
}
__device__ __forceinline__ void split2(float a, float b, uint32_t& hi, uint32_t& lo) {
    __nv_bfloat16 ah = __float2bfloat16(a), bh = __float2bfloat16(b);
    __nv_bfloat16 al = __float2bfloat16(a - __bfloat162float(ah));
    __nv_bfloat16 bl = __float2bfloat16(b - __bfloat162float(bh));
    hi = packbf(ah, bh);
    lo = packbf(al, bl);
}
__device__ __forceinline__ void mma16816(float* d, const uint4& a, uint32_t b0, uint32_t b1) {
    asm volatile(
        "mma.sync.aligned.m16n8k16.row.col.f32.bf16.bf16.f32 "
        "{%0,%1,%2,%3}, {%4,%5,%6,%7}, {%8,%9}, {%0,%1,%2,%3};"
        : "+f"(d[0]), "+f"(d[1]), "+f"(d[2]), "+f"(d[3])
        : "r"(a.x), "r"(a.y), "r"(a.z), "r"(a.w), "r"(b0), "r"(b1));
}
__device__ __forceinline__ float sigmoid_fast(float x) { return 1.f / (1.f + __expf(-x)); }
__device__ __forceinline__ float tanh_fast(float x) { float e = __expf(2.f * x); return 1.f - 2.f / (e + 1.f); }

// orig gate col c = gate*512 + hcol -> pc = (hcol/8)*32 + gate*8 + hcol%8
__device__ __forceinline__ int cperm(int c) {
    int g = c >> 9, hc = c & 511;
    return ((hc >> 3) << 5) + (g << 3) + (hc & 7);
}

// ---------------- init ----------------
__global__ void init_kernel() {
    int i = blockIdx.x * blockDim.x + threadIdx.x;
    if (i == 0) { g_bar_l2 = 0; g_bar_epoch = 0; }
    if (i < 8 * 32) g_bar_l1[i] = 0u;
    if (i < 8 * 32 * 32) {
        g_hfh[0][i] = make_uint4(0, 0, 0, 0);
        g_hfl[0][i] = make_uint4(0, 0, 0, 0);
    }
}

// ---------------- U fragment prep ----------------
__global__ __launch_bounds__(256) void uf_prep(const float* __restrict__ U) {
    int i = blockIdx.x * 256 + threadIdx.x;
    int l = i & 31, nt = (i >> 5) & 3, kt = (i >> 7) & 31, cta = i >> 12;
    int n = nt * 8 + (l >> 2);
    int k0 = kt * 16 + (l & 3) * 2;
    int c = (n >> 3) * 512 + cta * 8 + (n & 7);
    float u00 = U[(size_t)k0 * G4_ + c];
    float u01 = U[(size_t)(k0 + 1) * G4_ + c];
    float u10 = U[(size_t)(k0 + 8) * G4_ + c];
    float u11 = U[(size_t)(k0 + 9) * G4_ + c];
    uint32_t b0h, b0l, b1h, b1l;
    split2(u00, u01, b0h, b0l);
    split2(u10, u11, b1h, b1l);
    g_uf[i] = make_uint4(b0h, b1h, b0l, b1l);
}

// ---------------- x fragment prep ----------------
__global__ __launch_bounds__(256) void split_xf(const float* __restrict__ x) {
    size_t i = (size_t)blockIdx.x * 256 + threadIdx.x;
    int l = (int)(i & 31), kt = (int)((i >> 5) & 15);
    int rg = (int)(i >> 9);
    int row = rg * 16 + (l >> 2);
    int k0 = kt * 16 + (l & 3) * 2;
    uint32_t hi[4], lo[4];
#pragma unroll
    for (int kh = 0; kh < 2; kh++)
#pragma unroll
        for (int rh = 0; rh < 2; rh++) {
            float2 v = *(const float2*)&x[(size_t)(row + 8 * rh) * D_ + k0 + 8 * kh];
            split2(v.x, v.y, hi[kh * 2 + rh], lo[kh * 2 + rh]);
        }
    g_xfh[i] = make_uint4(hi[0], hi[1], hi[2], hi[3]);
    g_xfl[i] = make_uint4(lo[0], lo[1], lo[2], lo[3]);
}

// ---------------- W fragment prep ----------------
__global__ __launch_bounds__(256) void wf_prep(const float* __restrict__ Wm) {
    int i = blockIdx.x * 256 + threadIdx.x;
    int l = i & 31, nc = (i >> 5) & 15, kt = (i >> 9) & 15, cb = i >> 13;
    int n = cb * 128 + nc * 8 + (l >> 2);
    int k0 = kt * 16 + (l & 3) * 2;
    float u00 = Wm[(size_t)k0 * G4_ + n];
    float u01 = Wm[(size_t)(k0 + 1) * G4_ + n];
    float u10 = Wm[(size_t)(k0 + 8) * G4_ + n];
    float u11 = Wm[(size_t)(k0 + 9) * G4_ + n];
    uint32_t b0h, b0l, b1h, b1l;
    split2(u00, u01, b0h, b0l);
    split2(u10, u11, b1h, b1l);
    g_wf[i] = make_uint4(b0h, b1h, b0l, b1l);
}

// ---------------- phase 1: xW = x @ W + bias (mma.sync) ----------------
__global__ __launch_bounds__(256) void xw_mma(const float* __restrict__ bias) {
    const int tid = threadIdx.x;
    const int w = tid >> 5, l = tid & 31;
    const int cb = blockIdx.x, rb = blockIdx.y;
    const int wr = w & 3, wc = w >> 2;

    float acc[2][8][4];
#pragma unroll
    for (int mt = 0; mt < 2; mt++)
#pragma unroll
        for (int nt = 0; nt < 8; nt++)
#pragma unroll
            for (int q = 0; q < 4; q++) acc[mt][nt][q] = 0.f;

#pragma unroll 4
    for (int kt = 0; kt < 16; kt++) {
        uint4 bf[8];
#pragma unroll
        for (int nt = 0; nt < 8; nt++)
            bf[nt] = __ldg(&g_wf[(((cb * 16 + kt) * 16) + wc * 8 + nt) * 32 + l]);
#pragma unroll
        for (int mt = 0; mt < 2; mt++) {
            size_t rg = (size_t)rb * 8 + wr * 2 + mt;
            uint4 ah = __ldg(&g_xfh[(rg * 16 + kt) * 32 + l]);
            uint4 al = __ldg(&g_xfl[(rg * 16 + kt) * 32 + l]);
#pragma unroll
            for (int nt = 0; nt < 8; nt++) {
                mma16816(acc[mt][nt], ah, bf[nt].x, bf[nt].y);
                mma16816(acc[mt][nt], ah, bf[nt].z, bf[nt].w);
                mma16816(acc[mt][nt], al, bf[nt].x, bf[nt].y);
            }
        }
    }

#pragma unroll
    for (int mt = 0; mt < 2; mt++) {
        int r0 = rb * 128 + wr * 32 + mt * 16 + (l >> 2);
#pragma unroll
        for (int nt = 0; nt < 8; nt++) {
            int c = cb * 128 + wc * 64 + nt * 8 + (l & 3) * 2;
            int pc = cperm(c);
            float2 bv = __ldg((const float2*)&bias[c]);
            *(float2*)&g_xw[(size_t)r0 * G4_ + pc] =
                make_float2(acc[mt][nt][0] + bv.x, acc[mt][nt][1] + bv.y);
            *(float2*)&g_xw[(size_t)(r0 + 8) * G4_ + pc] =
                make_float2(acc[mt][nt][2] + bv.x, acc[mt][nt][3] + bv.y);
        }
    }
}

// ---------------- phase 2: persistent mma.sync recurrence ----------------
// 64 CTAs x 512 thr. Warp (mq=w>>2, kq=w&3): M=32 (2 mt), K=64 (8 kt), N=32.
// A frags: 3-deep register ring (direct LDG, L2). U frags: single-buffer L1.
#define SPAD  34
#define XPAD  36
#define SRED_ELEMS (4 * 128 * SPAD)
#define SMEM_ELEMS (SRED_ELEMS + 128 * XPAD)

__global__ __launch_bounds__(RTHR, 1) void lstm_rec(float* __restrict__ out,
                                                    int write_hc) {
    extern __shared__ float smemf[];
    float* sred = smemf;
    float* xw_s = smemf + SRED_ELEMS;

    const int tid = threadIdx.x;
    const int w = tid >> 5, l = tid & 31;
    const int cta = blockIdx.x;
    const int mq = w >> 2, kq = w & 3;

    // epilogue role: 2 cells = row_e x hcols {2hp, 2hp+1}
    const int row_e = tid >> 2, hp = tid & 3;
    const int kt_w = cta >> 1;
    const int regb = (cta & 1) * 2 + ((row_e >> 3) & 1);
    const size_t fragidx = ((size_t)(row_e >> 4) * 32 + kt_w) * 32 + (row_e & 7) * 4 + hp;

    const uint4* __restrict__ ub = g_uf + (size_t)cta * 4096;

    const int xw_rw0 = w * 8 + (l >> 3);
    const int xw_co  = cta * 32 + (l & 7) * 4;

    float creg[2] = {0.f, 0.f};
    float hlast[2];

    // xw prefetch for t = 0
    float4 xr[2];
#pragma unroll
    for (int j = 0; j < 2; j++)
        xr[j] = __ldcg((const float4*)&g_xw[((size_t)(xw_rw0 + j * 4) * T_ + 0) * G4_ + xw_co]);

#define LOAD_ASLOT(dst, Ah_, Al_, i_) do {                                       \
    const int kt_ = kq * 8 + (i_);                                               \
    (dst)[0] = __ldcg(&(Ah_)[(((mq * 2 + 0) * 32) + kt_) * 32 + l]);             \
    (dst)[1] = __ldcg(&(Ah_)[(((mq * 2 + 1) * 32) + kt_) * 32 + l]);             \
    (dst)[2] = __ldcg(&(Al_)[(((mq * 2 + 0) * 32) + kt_) * 32 + l]);             \
    (dst)[3] = __ldcg(&(Al_)[(((mq * 2 + 1) * 32) + kt_) * 32 + l]);             \
} while (0)

    for (int t = 0; t < T_; t++) {
        const int p = t & 1;
        const uint4* __restrict__ Ah = g_hfh[p];
        const uint4* __restrict__ Al = g_hfl[p];

        // A ring prologue: iters 0, 1
        uint4 ring[3][4];
        LOAD_ASLOT(ring[0], Ah, Al, 0);
        LOAD_ASLOT(ring[1], Ah, Al, 1);

        float acc[2][4][4];
#pragma unroll
        for (int mt = 0; mt < 2; mt++)
#pragma unroll
            for (int nt = 0; nt < 4; nt++)
#pragma unroll
                for (int q = 0; q < 4; q++) acc[mt][nt][q] = 0.f;

#pragma unroll
        for (int i = 0; i < 8; i++) {
            const int s = i % 3;
            if (i < 6) LOAD_ASLOT(ring[(i + 2) % 3], Ah, Al, i + 2);   // 2-iter lookahead
            const int kt = kq * 8 + i;
            uint4 bf[4];
#pragma unroll
            for (int nt = 0; nt < 4; nt++)
                bf[nt] = __ldg(&ub[(kt * 4 + nt) * 32 + l]);
#pragma unroll
            for (int nt = 0; nt < 4; nt++) {
                mma16816(acc[0][nt], ring[s][0], bf[nt].x, bf[nt].y);
                mma16816(acc[0][nt], ring[s][0], bf[nt].z, bf[nt].w);
                mma16816(acc[0][nt], ring[s][2], bf[nt].x, bf[nt].y);
                mma16816(acc[1][nt], ring[s][1], bf[nt].x, bf[nt].y);
                mma16816(acc[1][nt], ring[s][1], bf[nt].z, bf[nt].w);
                mma16816(acc[1][nt], ring[s][3], bf[nt].x, bf[nt].y);
            }
        }

        // ---- partials + xw to smem ----
        {
            const int row0 = (l >> 2), n0 = 2 * (l & 3);
#pragma unroll
            for (int mt = 0; mt < 2; mt++)
#pragma unroll
                for (int nt = 0; nt < 4; nt++) {
                    int s = (kq * 128 + (mq * 2 + mt) * 16 + row0) * SPAD + nt * 8 + n0;
                    *(float2*)&sred[s]            = make_float2(acc[mt][nt][0], acc[mt][nt][1]);
                    *(float2*)&sred[s + 8 * SPAD] = make_float2(acc[mt][nt][2], acc[mt][nt][3]);
                }
#pragma unroll
            for (int j = 0; j < 2; j++)
                *(float4*)&xw_s[(xw_rw0 + j * 4) * XPAD + (l & 7) * 4] = xr[j];
        }
        __syncthreads();

        // ---- reduce + cell update ----
        float2 gsum[4];
#pragma unroll
        for (int g = 0; g < 4; g++) {
            float2 s = *(const float2*)&xw_s[row_e * XPAD + g * 8 + 2 * hp];
#pragma unroll
            for (int q2 = 0; q2 < 4; q2++) {
                float2 v = *(const float2*)&sred[(q2 * 128 + row_e) * SPAD + g * 8 + 2 * hp];
                s.x += v.x; s.y += v.y;
            }
            gsum[g] = s;
        }
        float hnew[2];
#pragma unroll
        for (int q = 0; q < 2; q++) {
            float gi = q ? gsum[0].y : gsum[0].x;
            float gf = q ? gsum[1].y : gsum[1].x;
            float gg = q ? gsum[2].y : gsum[2].x;
            float go = q ? gsum[3].y : gsum[3].x;
            float iv = sigmoid_fast(gi);
            float fv = sigmoid_fast(gf);
            float gv = tanh_fast(gg);
            float ov = sigmoid_fast(go);
            float c = fv * creg[q] + iv * gv;
            creg[q] = c;
            float h = ov * tanh_fast(c);
            hnew[q] = h;
            hlast[q] = h;
        }

        // h fragment write for next step (must precede the barrier arrival)
        {
            uint32_t hi, lo;
            split2(hnew[0], hnew[1], hi, lo);
            *(uint32_t*)((char*)g_hfh[1 - p] + fragidx * 16 + regb * 4) = hi;
            *(uint32_t*)((char*)g_hfl[1 - p] + fragidx * 16 + regb * 4) = lo;
        }

        if (t < T_ - 1) {
            const unsigned tgt = (unsigned)(t + 1);
            __threadfence();
            __syncthreads();
            // arrive FIRST (tree: 8 leaves x 8, monotonic counters)
            if (tid == 0) {
                unsigned old = atomicAdd(&g_bar_l1[(cta & 7) * 32], 1u);
                if (old == 8u * tgt - 1u) {
                    unsigned old2 = atomicAdd(&g_bar_l2, 1u);
                    if (old2 == 8u * tgt - 1u) {
                        __threadfence();
                        g_bar_epoch = tgt;
                    }
                }
            }
            // overlap with the barrier: out store + next-step xw prefetch
            *(float2*)&out[((size_t)row_e * T_ + t) * HS_ + cta * 8 + 2 * hp] =
                make_float2(hnew[0], hnew[1]);
#pragma unroll
            for (int j = 0; j < 2; j++)
                xr[j] = __ldcg((const float4*)&g_xw[((size_t)(xw_rw0 + j * 4) * T_ + (t + 1)) * G4_ + xw_co]);
            if (tid == 0) {
                while (g_bar_epoch < tgt) { }
                __threadfence();
            }
            __syncthreads();
        } else {
            *(float2*)&out[((size_t)row_e * T_ + t) * HS_ + cta * 8 + 2 * hp] =
                make_float2(hnew[0], hnew[1]);
        }
    }

    if (write_hc) {
        const size_t OH = (size_t)B_ * T_ * HS_;
        *(float2*)&out[OH + (size_t)row_e * HS_ + cta * 8 + 2 * hp] =
            make_float2(hlast[0], hlast[1]);
        *(float2*)&out[OH + (size_t)B_ * HS_ + (size_t)row_e * HS_ + cta * 8 + 2 * hp] =
            make_float2(creg[0], creg[1]);
    }
#undef LOAD_ASLOT
}

// ---------------- launch ----------------
extern "C" void kernel_launch(void* const* d_in, const int* in_sizes, int n_in,
                              void* d_out, int out_size) {
    const float* x    = (const float*)d_in[0];
    const float* Wm   = (const float*)d_in[1];
    const float* U    = (const float*)d_in[2];
    const float* bias = (const float*)d_in[3];
    float* out = (float*)d_out;
    (void)in_sizes; (void)n_in;

    const int smem_rec = SMEM_ELEMS * (int)sizeof(float);   // 88064 B
    cudaFuncSetAttribute(lstm_rec, cudaFuncAttributeMaxDynamicSharedMemorySize, smem_rec);

    const long long need_hc = (long long)B_ * T_ * HS_ + 2LL * B_ * HS_;
    int write_hc = ((long long)out_size >= need_hc) ? 1 : 0;

    init_kernel<<<32, 256>>>();
    split_xf<<<16384, 256>>>(x);
    wf_prep<<<512, 256>>>(Wm);
    uf_prep<<<1024, 256>>>(U);
    xw_mma<<<dim3(16, 1024), 256>>>(bias);
    lstm_rec<<<RCTA, RTHR, smem_rec>>>(out, write_hc);
}

// round 12
// speedup vs baseline: 1.0616x; 1.0444x over previous
#include <cuda_runtime.h>
#include <cuda_bf16.h>
#include <cstdint>

#define B_   128
#define T_   1024
#define D_   256
#define HS_  512
#define G4_  2048
#define M1_  (B_ * T_)

#define RCTA 64
#define RTHR 512

// ---------------- device scratch ----------------
__device__ float g_xw[(size_t)M1_ * G4_];            // [(row*T+t)*2048 + pc]
__device__ uint4 g_uf[RCTA * 32 * 4 * 32];           // U frags [cta][kt][nt][lane]
__device__ uint4 g_xfh[(size_t)8192 * 16 * 32];      // x A-frags hi
__device__ uint4 g_xfl[(size_t)8192 * 16 * 32];      // x A-frags lo
__device__ uint4 g_wf[16 * 16 * 16 * 32];            // W B-frags
__device__ uint4 g_hfh[2][8 * 32 * 32];              // h hi A-frags
__device__ uint4 g_hfl[2][8 * 32 * 32];              // h lo A-frags
__device__ unsigned int g_bar_l1[8 * 32];            // tree barrier leaves (128B stride)
__device__ unsigned int g_bar_l2;                    // tree barrier root
__device__ unsigned int g_bar_epoch;

// ---------------- helpers ----------------
__device__ __forceinline__ uint32_t packbf(__nv_bfloat16 a, __nv_bfloat16 b) {
    return ((uint32_t)(*(uint16_t*)&b) << 16) | (uint32_t)(*(uint16_t*)&a);
}
__device__ __forceinline__ void split2(float a, float b, uint32_t& hi, uint32_t& lo) {
    __nv_bfloat16 ah = __float2bfloat16(a), bh = __float2bfloat16(b);
    __nv_bfloat16 al = __float2bfloat16(a - __bfloat162float(ah));
    __nv_bfloat16 bl = __float2bfloat16(b - __bfloat162float(bh));
    hi = packbf(ah, bh);
    lo = packbf(al, bl);
}
__device__ __forceinline__ void mma16816(float* d, const uint4& a, uint32_t b0, uint32_t b1) {
    asm volatile(
        "mma.sync.aligned.m16n8k16.row.col.f32.bf16.bf16.f32 "
        "{%0,%1,%2,%3}, {%4,%5,%6,%7}, {%8,%9}, {%0,%1,%2,%3};"
        : "+f"(d[0]), "+f"(d[1]), "+f"(d[2]), "+f"(d[3])
        : "r"(a.x), "r"(a.y), "r"(a.z), "r"(a.w), "r"(b0), "r"(b1));
}
__device__ __forceinline__ unsigned atom_add_release(unsigned* p, unsigned v) {
    unsigned old;
    asm volatile("atom.release.gpu.global.add.u32 %0, [%1], %2;"
                 : "=r"(old) : "l"(p), "r"(v) : "memory");
    return old;
}
__device__ __forceinline__ void st_release(unsigned* p, unsigned v) {
    asm volatile("st.release.gpu.global.u32 [%0], %1;" :: "l"(p), "r"(v) : "memory");
}
__device__ __forceinline__ unsigned ld_acquire(const unsigned* p) {
    unsigned v;
    asm volatile("ld.acquire.gpu.global.u32 %0, [%1];" : "=r"(v) : "l"(p) : "memory");
    return v;
}
__device__ __forceinline__ float sigmoid_fast(float x) { return 1.f / (1.f + __expf(-x)); }
__device__ __forceinline__ float tanh_fast(float x) { float e = __expf(2.f * x); return 1.f - 2.f / (e + 1.f); }

// orig gate col c = gate*512 + hcol -> pc = (hcol/8)*32 + gate*8 + hcol%8
__device__ __forceinline__ int cperm(int c) {
    int g = c >> 9, hc = c & 511;
    return ((hc >> 3) << 5) + (g << 3) + (hc & 7);
}

// ---------------- merged prep: split_xf | wf | uf | init ----------------
// grid = 16384 + 512 + 1024 + 32 = 17952 blocks x 256
__global__ __launch_bounds__(256) void prep_all(const float* __restrict__ x,
                                                const float* __restrict__ Wm,
                                                const float* __restrict__ U) {
    const int bid = blockIdx.x;
    const int tid = threadIdx.x;
    if (bid < 16384) {
        // ---- x A-fragment split ----
        size_t i = (size_t)bid * 256 + tid;
        int l = (int)(i & 31), kt = (int)((i >> 5) & 15);
        int rg = (int)(i >> 9);
        int row = rg * 16 + (l >> 2);
        int k0 = kt * 16 + (l & 3) * 2;
        uint32_t hi[4], lo[4];
#pragma unroll
        for (int kh = 0; kh < 2; kh++)
#pragma unroll
            for (int rh = 0; rh < 2; rh++) {
                float2 v = *(const float2*)&x[(size_t)(row + 8 * rh) * D_ + k0 + 8 * kh];
                split2(v.x, v.y, hi[kh * 2 + rh], lo[kh * 2 + rh]);
            }
        g_xfh[i] = make_uint4(hi[0], hi[1], hi[2], hi[3]);
        g_xfl[i] = make_uint4(lo[0], lo[1], lo[2], lo[3]);
    } else if (bid < 16896) {
        // ---- W B-fragment prep ----
        int i = (bid - 16384) * 256 + tid;
        int l = i & 31, nc = (i >> 5) & 15, kt = (i >> 9) & 15, cb = i >> 13;
        int n = cb * 128 + nc * 8 + (l >> 2);
        int k0 = kt * 16 + (l & 3) * 2;
        float u00 = Wm[(size_t)k0 * G4_ + n];
        float u01 = Wm[(size_t)(k0 + 1) * G4_ + n];
        float u10 = Wm[(size_t)(k0 + 8) * G4_ + n];
        float u11 = Wm[(size_t)(k0 + 9) * G4_ + n];
        uint32_t b0h, b0l, b1h, b1l;
        split2(u00, u01, b0h, b0l);
        split2(u10, u11, b1h, b1l);
        g_wf[i] = make_uint4(b0h, b1h, b0l, b1l);
    } else if (bid < 17920) {
        // ---- U fragment prep ----
        int i = (bid - 16896) * 256 + tid;
        int l = i & 31, nt = (i >> 5) & 3, kt = (i >> 7) & 31, cta = i >> 12;
        int n = nt * 8 + (l >> 2);
        int k0 = kt * 16 + (l & 3) * 2;
        int c = (n >> 3) * 512 + cta * 8 + (n & 7);
        float u00 = U[(size_t)k0 * G4_ + c];
        float u01 = U[(size_t)(k0 + 1) * G4_ + c];
        float u10 = U[(size_t)(k0 + 8) * G4_ + c];
        float u11 = U[(size_t)(k0 + 9) * G4_ + c];
        uint32_t b0h, b0l, b1h, b1l;
        split2(u00, u01, b0h, b0l);
        split2(u10, u11, b1h, b1l);
        g_uf[i] = make_uint4(b0h, b1h, b0l, b1l);
    } else {
        // ---- init: h0 frags + barrier state ----
        int i = (bid - 17920) * 256 + tid;           // 0..8191
        if (i == 0) { g_bar_l2 = 0; g_bar_epoch = 0; }
        if (i < 8 * 32) g_bar_l1[i] = 0u;
        g_hfh[0][i] = make_uint4(0, 0, 0, 0);
        g_hfl[0][i] = make_uint4(0, 0, 0, 0);
    }
}

// ---------------- phase 1: xW = x @ W + bias (mma.sync) ----------------
__global__ __launch_bounds__(256) void xw_mma(const float* __restrict__ bias) {
    const int tid = threadIdx.x;
    const int w = tid >> 5, l = tid & 31;
    const int cb = blockIdx.x, rb = blockIdx.y;
    const int wr = w & 3, wc = w >> 2;

    float acc[2][8][4];
#pragma unroll
    for (int mt = 0; mt < 2; mt++)
#pragma unroll
        for (int nt = 0; nt < 8; nt++)
#pragma unroll
            for (int q = 0; q < 4; q++) acc[mt][nt][q] = 0.f;

#pragma unroll 4
    for (int kt = 0; kt < 16; kt++) {
        uint4 bf[8];
#pragma unroll
        for (int nt = 0; nt < 8; nt++)
            bf[nt] = __ldg(&g_wf[(((cb * 16 + kt) * 16) + wc * 8 + nt) * 32 + l]);
#pragma unroll
        for (int mt = 0; mt < 2; mt++) {
            size_t rg = (size_t)rb * 8 + wr * 2 + mt;
            uint4 ah = __ldg(&g_xfh[(rg * 16 + kt) * 32 + l]);
            uint4 al = __ldg(&g_xfl[(rg * 16 + kt) * 32 + l]);
#pragma unroll
            for (int nt = 0; nt < 8; nt++) {
                mma16816(acc[mt][nt], ah, bf[nt].x, bf[nt].y);
                mma16816(acc[mt][nt], ah, bf[nt].z, bf[nt].w);
                mma16816(acc[mt][nt], al, bf[nt].x, bf[nt].y);
            }
        }
    }

#pragma unroll
    for (int mt = 0; mt < 2; mt++) {
        int r0 = rb * 128 + wr * 32 + mt * 16 + (l >> 2);
#pragma unroll
        for (int nt = 0; nt < 8; nt++) {
            int c = cb * 128 + wc * 64 + nt * 8 + (l & 3) * 2;
            int pc = cperm(c);
            float2 bv = __ldg((const float2*)&bias[c]);
            *(float2*)&g_xw[(size_t)r0 * G4_ + pc] =
                make_float2(acc[mt][nt][0] + bv.x, acc[mt][nt][1] + bv.y);
            *(float2*)&g_xw[(size_t)(r0 + 8) * G4_ + pc] =
                make_float2(acc[mt][nt][2] + bv.x, acc[mt][nt][3] + bv.y);
        }
    }
}

// ---------------- phase 2: persistent mma.sync recurrence ----------------
// 64 CTAs x 512 thr. Warp (mq=w>>2, kq=w&3): M=32 (2 mt), K=64 (8 kt), N=32.
// A frags: 2-deep register double-buffer (direct LDG, L2). U frags: L1 (__ldg),
// hot across steps now that no gpu-scope fence flushes L1D.
#define SPAD  34
#define XPAD  36
#define SRED_ELEMS (4 * 128 * SPAD)
#define SMEM_ELEMS (SRED_ELEMS + 128 * XPAD)

__global__ __launch_bounds__(RTHR, 1) void lstm_rec(float* __restrict__ out,
                                                    int write_hc) {
    extern __shared__ float smemf[];
    float* sred = smemf;
    float* xw_s = smemf + SRED_ELEMS;

    const int tid = threadIdx.x;
    const int w = tid >> 5, l = tid & 31;
    const int cta = blockIdx.x;
    const int mq = w >> 2, kq = w & 3;

    // epilogue role: 2 cells = row_e x hcols {2hp, 2hp+1}
    const int row_e = tid >> 2, hp = tid & 3;
    const int kt_w = cta >> 1;
    const int regb = (cta & 1) * 2 + ((row_e >> 3) & 1);
    const size_t fragidx = ((size_t)(row_e >> 4) * 32 + kt_w) * 32 + (row_e & 7) * 4 + hp;

    const uint4* __restrict__ ub = g_uf + (size_t)cta * 4096;

    const int xw_rw0 = w * 8 + (l >> 3);
    const int xw_co  = cta * 32 + (l & 7) * 4;

    float creg[2] = {0.f, 0.f};
    float hlast[2];

    // xw prefetch for t = 0
    float4 xr[2];
#pragma unroll
    for (int j = 0; j < 2; j++)
        xr[j] = __ldcg((const float4*)&g_xw[((size_t)(xw_rw0 + j * 4) * T_ + 0) * G4_ + xw_co]);

    for (int t = 0; t < T_; t++) {
        const int p = t & 1;
        const uint4* __restrict__ Ah = g_hfh[p];
        const uint4* __restrict__ Al = g_hfl[p];

        float acc[2][4][4];
#pragma unroll
        for (int mt = 0; mt < 2; mt++)
#pragma unroll
            for (int nt = 0; nt < 4; nt++)
#pragma unroll
                for (int q = 0; q < 4; q++) acc[mt][nt][q] = 0.f;

        // ---- mainloop: kt = kq*8 + i, double-buffered A ----
        uint4 bh[2][2], bl[2][2];
#pragma unroll
        for (int mt = 0; mt < 2; mt++) {
            const int slot = (((mq * 2 + mt) * 32) + kq * 8) * 32 + l;
            bh[0][mt] = __ldcg(&Ah[slot]);
            bl[0][mt] = __ldcg(&Al[slot]);
        }
#pragma unroll
        for (int i = 0; i < 8; i++) {
            const int cur = i & 1;
            if (i < 7) {
                const int ktn = kq * 8 + i + 1;
#pragma unroll
                for (int mt = 0; mt < 2; mt++) {
                    const int slot = (((mq * 2 + mt) * 32) + ktn) * 32 + l;
                    bh[cur ^ 1][mt] = __ldcg(&Ah[slot]);
                    bl[cur ^ 1][mt] = __ldcg(&Al[slot]);
                }
            }
            const int kt = kq * 8 + i;
            uint4 bf[4];
#pragma unroll
            for (int nt = 0; nt < 4; nt++)
                bf[nt] = __ldg(&ub[(kt * 4 + nt) * 32 + l]);
#pragma unroll
            for (int mt = 0; mt < 2; mt++)
#pragma unroll
                for (int nt = 0; nt < 4; nt++) {
                    mma16816(acc[mt][nt], bh[cur][mt], bf[nt].x, bf[nt].y);
                    mma16816(acc[mt][nt], bh[cur][mt], bf[nt].z, bf[nt].w);
                    mma16816(acc[mt][nt], bl[cur][mt], bf[nt].x, bf[nt].y);
                }
        }

        // ---- partials + xw to smem ----
        {
            const int row0 = (l >> 2), n0 = 2 * (l & 3);
#pragma unroll
            for (int mt = 0; mt < 2; mt++)
#pragma unroll
                for (int nt = 0; nt < 4; nt++) {
                    int s = (kq * 128 + (mq * 2 + mt) * 16 + row0) * SPAD + nt * 8 + n0;
                    *(float2*)&sred[s]            = make_float2(acc[mt][nt][0], acc[mt][nt][1]);
                    *(float2*)&sred[s + 8 * SPAD] = make_float2(acc[mt][nt][2], acc[mt][nt][3]);
                }
#pragma unroll
            for (int j = 0; j < 2; j++)
                *(float4*)&xw_s[(xw_rw0 + j * 4) * XPAD + (l & 7) * 4] = xr[j];
        }
        __syncthreads();

        // ---- reduce + cell update ----
        float2 gsum[4];
#pragma unroll
        for (int g = 0; g < 4; g++) {
            float2 s = *(const float2*)&xw_s[row_e * XPAD + g * 8 + 2 * hp];
#pragma unroll
            for (int q2 = 0; q2 < 4; q2++) {
                float2 v = *(const float2*)&sred[(q2 * 128 + row_e) * SPAD + g * 8 + 2 * hp];
                s.x += v.x; s.y += v.y;
            }
            gsum[g] = s;
        }
        float hnew[2];
#pragma unroll
        for (int q = 0; q < 2; q++) {
            float gi = q ? gsum[0].y : gsum[0].x;
            float gf = q ? gsum[1].y : gsum[1].x;
            float gg = q ? gsum[2].y : gsum[2].x;
            float go = q ? gsum[3].y : gsum[3].x;
            float iv = sigmoid_fast(gi);
            float fv = sigmoid_fast(gf);
            float gv = tanh_fast(gg);
            float ov = sigmoid_fast(go);
            float c = fv * creg[q] + iv * gv;
            creg[q] = c;
            float h = ov * tanh_fast(c);
            hnew[q] = h;
            hlast[q] = h;
        }

        // h fragment write for next step (before barrier arrival)
        {
            uint32_t hi, lo;
            split2(hnew[0], hnew[1], hi, lo);
            *(uint32_t*)((char*)g_hfh[1 - p] + fragidx * 16 + regb * 4) = hi;
            *(uint32_t*)((char*)g_hfl[1 - p] + fragidx * 16 + regb * 4) = lo;
        }

        if (t < T_ - 1) {
            const unsigned tgt = (unsigned)(t + 1);
            __syncthreads();   // all threads' h stores precede tid0's release-arrive
            // arrive FIRST (tree: 8 leaves x 8, monotonic counters, release semantics)
            if (tid == 0) {
                unsigned old = atom_add_release(&g_bar_l1[(cta & 7) * 32], 1u);
                if (old == 8u * tgt - 1u) {
                    unsigned old2 = atom_add_release(&g_bar_l2, 1u);
                    if (old2 == 8u * tgt - 1u)
                        st_release(&g_bar_epoch, tgt);
                }
            }
            // overlap with the barrier: out store + next-step xw prefetch
            *(float2*)&out[((size_t)row_e * T_ + t) * HS_ + cta * 8 + 2 * hp] =
                make_float2(hnew[0], hnew[1]);
#pragma unroll
            for (int j = 0; j < 2; j++)
                xr[j] = __ldcg((const float4*)&g_xw[((size_t)(xw_rw0 + j * 4) * T_ + (t + 1)) * G4_ + xw_co]);
            if (tid == 0) {
                while (ld_acquire(&g_bar_epoch) < tgt) { }
            }
            __syncthreads();
        } else {
            *(float2*)&out[((size_t)row_e * T_ + t) * HS_ + cta * 8 + 2 * hp] =
                make_float2(hnew[0], hnew[1]);
        }
    }

    if (write_hc) {
        const size_t OH = (size_t)B_ * T_ * HS_;
        *(float2*)&out[OH + (size_t)row_e * HS_ + cta * 8 + 2 * hp] =
            make_float2(hlast[0], hlast[1]);
        *(float2*)&out[OH + (size_t)B_ * HS_ + (size_t)row_e * HS_ + cta * 8 + 2 * hp] =
            make_float2(creg[0], creg[1]);
    }
}

// ---------------- launch ----------------
extern "C" void kernel_launch(void* const* d_in, const int* in_sizes, int n_in,
                              void* d_out, int out_size) {
    const float* x    = (const float*)d_in[0];
    const float* Wm   = (const float*)d_in[1];
    const float* U    = (const float*)d_in[2];
    const float* bias = (const float*)d_in[3];
    float* out = (float*)d_out;
    (void)in_sizes; (void)n_in;

    const int smem_rec = SMEM_ELEMS * (int)sizeof(float);   // 88064 B
    cudaFuncSetAttribute(lstm_rec, cudaFuncAttributeMaxDynamicSharedMemorySize, smem_rec);

    const long long need_hc = (long long)B_ * T_ * HS_ + 2LL * B_ * HS_;
    int write_hc = ((long long)out_size >= need_hc) ? 1 : 0;

    prep_all<<<17952, 256>>>(x, Wm, U);
    xw_mma<<<dim3(16, 1024), 256>>>(bias);
    lstm_rec<<<RCTA, RTHR, smem_rec>>>(out, write_hc);
}

// round 13
// speedup vs baseline: 1.3484x; 1.2702x over previous
#include <cuda_runtime.h>
#include <cuda_bf16.h>
#include <cstdint>

#define B_   128
#define T_   1024
#define D_   256
#define HS_  512
#define G4_  2048
#define M1_  (B_ * T_)

#define RCTA 128
#define RTHR 512

// ---------------- device scratch ----------------
__device__ float g_xw[(size_t)M1_ * G4_];            // [(row*T+t)*2048 + pc]
__device__ uint4 g_uf[64 * 32 * 4 * 32];             // U frags [cg][kt][nt][lane]
__device__ uint4 g_xfh[(size_t)8192 * 16 * 32];      // x A-frags hi
__device__ uint4 g_xfl[(size_t)8192 * 16 * 32];      // x A-frags lo
__device__ uint4 g_wf[16 * 16 * 16 * 32];            // W B-frags
__device__ uint4 g_hfh[2][8 * 32 * 32];              // h hi A-frags
__device__ uint4 g_hfl[2][8 * 32 * 32];              // h lo A-frags
__device__ unsigned int g_bar_l1[16 * 32];           // tree barrier leaves (128B stride)
__device__ unsigned int g_bar_l2;                    // tree barrier root
__device__ unsigned int g_bar_epoch;

// ---------------- helpers ----------------
__device__ __forceinline__ uint32_t packbf(__nv_bfloat16 a, __nv_bfloat16 b) {
    return ((uint32_t)(*(uint16_t*)&b) << 16) | (uint32_t)(*(uint16_t*)&a);
}
__device__ __forceinline__ void split2(float a, float b, uint32_t& hi, uint32_t& lo) {
    __nv_bfloat16 ah = __float2bfloat16(a), bh = __float2bfloat16(b);
    __nv_bfloat16 al = __float2bfloat16(a - __bfloat162float(ah));
    __nv_bfloat16 bl = __float2bfloat16(b - __bfloat162float(bh));
    hi = packbf(ah, bh);
    lo = packbf(al, bl);
}
__device__ __forceinline__ void mma16816(float* d, const uint4& a, uint32_t b0, uint32_t b1) {
    asm volatile(
        "mma.sync.aligned.m16n8k16.row.col.f32.bf16.bf16.f32 "
        "{%0,%1,%2,%3}, {%4,%5,%6,%7}, {%8,%9}, {%0,%1,%2,%3};"
        : "+f"(d[0]), "+f"(d[1]), "+f"(d[2]), "+f"(d[3])
        : "r"(a.x), "r"(a.y), "r"(a.z), "r"(a.w), "r"(b0), "r"(b1));
}
__device__ __forceinline__ unsigned atom_add_release(unsigned* p, unsigned v) {
    unsigned old;
    asm volatile("atom.release.gpu.global.add.u32 %0, [%1], %2;"
                 : "=r"(old) : "l"(p), "r"(v) : "memory");
    return old;
}
__device__ __forceinline__ void st_release(unsigned* p, unsigned v) {
    asm volatile("st.release.gpu.global.u32 [%0], %1;" :: "l"(p), "r"(v) : "memory");
}
__device__ __forceinline__ unsigned ld_acquire(const unsigned* p) {
    unsigned v;
    asm volatile("ld.acquire.gpu.global.u32 %0, [%1];" : "=r"(v) : "l"(p) : "memory");
    return v;
}
__device__ __forceinline__ float sigmoid_fast(float x) { return 1.f / (1.f + __expf(-x)); }
__device__ __forceinline__ float tanh_fast(float x) { float e = __expf(2.f * x); return 1.f - 2.f / (e + 1.f); }

// orig gate col c = gate*512 + hcol -> pc = (hcol/8)*32 + gate*8 + hcol%8
__device__ __forceinline__ int cperm(int c) {
    int g = c >> 9, hc = c & 511;
    return ((hc >> 3) << 5) + (g << 3) + (hc & 7);
}

// ---------------- merged prep: split_xf | wf | uf | init ----------------
__global__ __launch_bounds__(256) void prep_all(const float* __restrict__ x,
                                                const float* __restrict__ Wm,
                                                const float* __restrict__ U) {
    const int bid = blockIdx.x;
    const int tid = threadIdx.x;
    if (bid < 16384) {
        size_t i = (size_t)bid * 256 + tid;
        int l = (int)(i & 31), kt = (int)((i >> 5) & 15);
        int rg = (int)(i >> 9);
        int row = rg * 16 + (l >> 2);
        int k0 = kt * 16 + (l & 3) * 2;
        uint32_t hi[4], lo[4];
#pragma unroll
        for (int kh = 0; kh < 2; kh++)
#pragma unroll
            for (int rh = 0; rh < 2; rh++) {
                float2 v = *(const float2*)&x[(size_t)(row + 8 * rh) * D_ + k0 + 8 * kh];
                split2(v.x, v.y, hi[kh * 2 + rh], lo[kh * 2 + rh]);
            }
        g_xfh[i] = make_uint4(hi[0], hi[1], hi[2], hi[3]);
        g_xfl[i] = make_uint4(lo[0], lo[1], lo[2], lo[3]);
    } else if (bid < 16896) {
        int i = (bid - 16384) * 256 + tid;
        int l = i & 31, nc = (i >> 5) & 15, kt = (i >> 9) & 15, cb = i >> 13;
        int n = cb * 128 + nc * 8 + (l >> 2);
        int k0 = kt * 16 + (l & 3) * 2;
        float u00 = Wm[(size_t)k0 * G4_ + n];
        float u01 = Wm[(size_t)(k0 + 1) * G4_ + n];
        float u10 = Wm[(size_t)(k0 + 8) * G4_ + n];
        float u11 = Wm[(size_t)(k0 + 9) * G4_ + n];
        uint32_t b0h, b0l, b1h, b1l;
        split2(u00, u01, b0h, b0l);
        split2(u10, u11, b1h, b1l);
        g_wf[i] = make_uint4(b0h, b1h, b0l, b1l);
    } else if (bid < 17920) {
        int i = (bid - 16896) * 256 + tid;
        int l = i & 31, nt = (i >> 5) & 3, kt = (i >> 7) & 31, cg = i >> 12;
        int n = nt * 8 + (l >> 2);
        int k0 = kt * 16 + (l & 3) * 2;
        int c = (n >> 3) * 512 + cg * 8 + (n & 7);
        float u00 = U[(size_t)k0 * G4_ + c];
        float u01 = U[(size_t)(k0 + 1) * G4_ + c];
        float u10 = U[(size_t)(k0 + 8) * G4_ + c];
        float u11 = U[(size_t)(k0 + 9) * G4_ + c];
        uint32_t b0h, b0l, b1h, b1l;
        split2(u00, u01, b0h, b0l);
        split2(u10, u11, b1h, b1l);
        g_uf[i] = make_uint4(b0h, b1h, b0l, b1l);
    } else {
        int i = (bid - 17920) * 256 + tid;           // 0..8191
        if (i == 0) { g_bar_l2 = 0; g_bar_epoch = 0; }
        if (i < 16 * 32) g_bar_l1[i] = 0u;
        g_hfh[0][i] = make_uint4(0, 0, 0, 0);
        g_hfl[0][i] = make_uint4(0, 0, 0, 0);
    }
}

// ---------------- phase 1: xW = x @ W + bias (mma.sync) ----------------
__global__ __launch_bounds__(256) void xw_mma(const float* __restrict__ bias) {
    const int tid = threadIdx.x;
    const int w = tid >> 5, l = tid & 31;
    const int cb = blockIdx.x, rb = blockIdx.y;
    const int wr = w & 3, wc = w >> 2;

    float acc[2][8][4];
#pragma unroll
    for (int mt = 0; mt < 2; mt++)
#pragma unroll
        for (int nt = 0; nt < 8; nt++)
#pragma unroll
            for (int q = 0; q < 4; q++) acc[mt][nt][q] = 0.f;

#pragma unroll 4
    for (int kt = 0; kt < 16; kt++) {
        uint4 bf[8];
#pragma unroll
        for (int nt = 0; nt < 8; nt++)
            bf[nt] = __ldg(&g_wf[(((cb * 16 + kt) * 16) + wc * 8 + nt) * 32 + l]);
#pragma unroll
        for (int mt = 0; mt < 2; mt++) {
            size_t rg = (size_t)rb * 8 + wr * 2 + mt;
            uint4 ah = __ldg(&g_xfh[(rg * 16 + kt) * 32 + l]);
            uint4 al = __ldg(&g_xfl[(rg * 16 + kt) * 32 + l]);
#pragma unroll
            for (int nt = 0; nt < 8; nt++) {
                mma16816(acc[mt][nt], ah, bf[nt].x, bf[nt].y);
                mma16816(acc[mt][nt], ah, bf[nt].z, bf[nt].w);
                mma16816(acc[mt][nt], al, bf[nt].x, bf[nt].y);
            }
        }
    }

#pragma unroll
    for (int mt = 0; mt < 2; mt++) {
        int r0 = rb * 128 + wr * 32 + mt * 16 + (l >> 2);
#pragma unroll
        for (int nt = 0; nt < 8; nt++) {
            int c = cb * 128 + wc * 64 + nt * 8 + (l & 3) * 2;
            int pc = cperm(c);
            float2 bv = __ldg((const float2*)&bias[c]);
            *(float2*)&g_xw[(size_t)r0 * G4_ + pc] =
                make_float2(acc[mt][nt][0] + bv.x, acc[mt][nt][1] + bv.y);
            *(float2*)&g_xw[(size_t)(r0 + 8) * G4_ + pc] =
                make_float2(acc[mt][nt][2] + bv.x, acc[mt][nt][3] + bv.y);
        }
    }
}

// ---------------- phase 2: persistent mma.sync recurrence ----------------
// 128 CTAs x 512 thr. cta = cg*2 + mh: cg owns 8 hcols (32 pc), mh owns row half.
// Warp (mq=w>>3, nq=(w>>2)&1, kq=w&3): M=32 (2 mt), N=16 (2 nt), K=128 (8 kt).
#define SPAD  34
#define XPAD  36
#define SRED_ELEMS (4 * 64 * SPAD)
#define SMEM_ELEMS (SRED_ELEMS + 64 * XPAD)

__global__ __launch_bounds__(RTHR, 1) void lstm_rec(float* __restrict__ out,
                                                    int write_hc) {
    extern __shared__ float smemf[];
    float* sred = smemf;
    float* xw_s = smemf + SRED_ELEMS;

    const int tid = threadIdx.x;
    const int w = tid >> 5, l = tid & 31;
    const int cta = blockIdx.x;
    const int cg = cta >> 1, mh = cta & 1;
    const int mq = w >> 3, nq = (w >> 2) & 1, kq = w & 3;

    // epilogue role (tid < 256): 2 cells = row x hcols {2hp, 2hp+1}
    const int rl = (tid & 255) >> 2, hp = tid & 3;
    const int row_g = mh * 64 + rl;
    const size_t fragidx = ((size_t)(row_g >> 4) * 32 + (cg >> 1)) * 32 + (row_g & 7) * 4 + hp;
    const int regb = (cg & 1) * 2 + ((row_g >> 3) & 1);

    const uint4* __restrict__ ub = g_uf + (size_t)cg * 4096;

    const int xw_rwl = tid >> 3;                     // local row 0..63
    const int xw_co  = cg * 32 + (tid & 7) * 4;
    const int aslot_base = ((mh * 4 + mq * 2) * 32) * 32 + l;   // + mt*1024 + kt*32

    float creg[2] = {0.f, 0.f};
    float hlast[2];

    // xw prefetch for t = 0
    float4 xr = __ldcg((const float4*)&g_xw[((size_t)(mh * 64 + xw_rwl) * T_ + 0) * G4_ + xw_co]);

    for (int t = 0; t < T_; t++) {
        const int p = t & 1;
        const uint4* __restrict__ Ah = g_hfh[p];
        const uint4* __restrict__ Al = g_hfl[p];

        float acc[2][2][4];
#pragma unroll
        for (int mt = 0; mt < 2; mt++)
#pragma unroll
            for (int nt = 0; nt < 2; nt++)
#pragma unroll
                for (int q = 0; q < 4; q++) acc[mt][nt][q] = 0.f;

        // ---- mainloop: kt = kq*8 + i, double-buffered A ----
        uint4 bh[2][2], bl[2][2];
#pragma unroll
        for (int mt = 0; mt < 2; mt++) {
            const int slot = aslot_base + mt * 1024 + (kq * 8) * 32;
            bh[0][mt] = __ldcg(&Ah[slot]);
            bl[0][mt] = __ldcg(&Al[slot]);
        }
#pragma unroll
        for (int i = 0; i < 8; i++) {
            const int cur = i & 1;
            if (i < 7) {
                const int ktn = kq * 8 + i + 1;
#pragma unroll
                for (int mt = 0; mt < 2; mt++) {
                    const int slot = aslot_base + mt * 1024 + ktn * 32;
                    bh[cur ^ 1][mt] = __ldcg(&Ah[slot]);
                    bl[cur ^ 1][mt] = __ldcg(&Al[slot]);
                }
            }
            const int kt = kq * 8 + i;
            uint4 bf[2];
#pragma unroll
            for (int nt = 0; nt < 2; nt++)
                bf[nt] = __ldg(&ub[(kt * 4 + nq * 2 + nt) * 32 + l]);
#pragma unroll
            for (int mt = 0; mt < 2; mt++)
#pragma unroll
                for (int nt = 0; nt < 2; nt++) {
                    mma16816(acc[mt][nt], bh[cur][mt], bf[nt].x, bf[nt].y);
                    mma16816(acc[mt][nt], bh[cur][mt], bf[nt].z, bf[nt].w);
                    mma16816(acc[mt][nt], bl[cur][mt], bf[nt].x, bf[nt].y);
                }
        }

        // ---- partials + xw to smem ----
        {
            const int row0 = (l >> 2), n0 = 2 * (l & 3);
#pragma unroll
            for (int mt = 0; mt < 2; mt++)
#pragma unroll
                for (int nt = 0; nt < 2; nt++) {
                    int s = (kq * 64 + mq * 32 + mt * 16 + row0) * SPAD + nq * 16 + nt * 8 + n0;
                    *(float2*)&sred[s]            = make_float2(acc[mt][nt][0], acc[mt][nt][1]);
                    *(float2*)&sred[s + 8 * SPAD] = make_float2(acc[mt][nt][2], acc[mt][nt][3]);
                }
            *(float4*)&xw_s[xw_rwl * XPAD + (tid & 7) * 4] = xr;
        }
        __syncthreads();

        // ---- reduce + cell update (tid < 256) ----
        float hnew[2];
        if (tid < 256) {
            float2 gsum[4];
#pragma unroll
            for (int g = 0; g < 4; g++) {
                float2 s = *(const float2*)&xw_s[rl * XPAD + g * 8 + 2 * hp];
#pragma unroll
                for (int q2 = 0; q2 < 4; q2++) {
                    float2 v = *(const float2*)&sred[(q2 * 64 + rl) * SPAD + g * 8 + 2 * hp];
                    s.x += v.x; s.y += v.y;
                }
                gsum[g] = s;
            }
#pragma unroll
            for (int q = 0; q < 2; q++) {
                float gi = q ? gsum[0].y : gsum[0].x;
                float gf = q ? gsum[1].y : gsum[1].x;
                float gg = q ? gsum[2].y : gsum[2].x;
                float go = q ? gsum[3].y : gsum[3].x;
                float iv = sigmoid_fast(gi);
                float fv = sigmoid_fast(gf);
                float gv = tanh_fast(gg);
                float ov = sigmoid_fast(go);
                float c = fv * creg[q] + iv * gv;
                creg[q] = c;
                float h = ov * tanh_fast(c);
                hnew[q] = h;
                hlast[q] = h;
            }
            // h fragment write for next step (before barrier arrival)
            uint32_t hi, lo;
            split2(hnew[0], hnew[1], hi, lo);
            *(uint32_t*)((char*)g_hfh[1 - p] + fragidx * 16 + regb * 4) = hi;
            *(uint32_t*)((char*)g_hfl[1 - p] + fragidx * 16 + regb * 4) = lo;
        }

        if (t < T_ - 1) {
            const unsigned tgt = (unsigned)(t + 1);
            __syncthreads();   // all h stores precede tid0's release-arrive
            if (tid == 0) {
                unsigned old = atom_add_release(&g_bar_l1[(cta & 15) * 32], 1u);
                if (old == 8u * tgt - 1u) {
                    unsigned old2 = atom_add_release(&g_bar_l2, 1u);
                    if (old2 == 16u * tgt - 1u)
                        st_release(&g_bar_epoch, tgt);
                }
            }
            // overlap with the barrier: out store + next-step xw prefetch
            if (tid < 256)
                *(float2*)&out[((size_t)row_g * T_ + t) * HS_ + cg * 8 + 2 * hp] =
                    make_float2(hnew[0], hnew[1]);
            xr = __ldcg((const float4*)&g_xw[((size_t)(mh * 64 + xw_rwl) * T_ + (t + 1)) * G4_ + xw_co]);
            if (tid == 0) {
                while (ld_acquire(&g_bar_epoch) < tgt) { }
            }
            __syncthreads();
        } else {
            if (tid < 256)
                *(float2*)&out[((size_t)row_g * T_ + t) * HS_ + cg * 8 + 2 * hp] =
                    make_float2(hnew[0], hnew[1]);
        }
    }

    if (write_hc && tid < 256) {
        const size_t OH = (size_t)B_ * T_ * HS_;
        *(float2*)&out[OH + (size_t)row_g * HS_ + cg * 8 + 2 * hp] =
            make_float2(hlast[0], hlast[1]);
        *(float2*)&out[OH + (size_t)B_ * HS_ + (size_t)row_g * HS_ + cg * 8 + 2 * hp] =
            make_float2(creg[0], creg[1]);
    }
}

// ---------------- launch ----------------
extern "C" void kernel_launch(void* const* d_in, const int* in_sizes, int n_in,
                              void* d_out, int out_size) {
    const float* x    = (const float*)d_in[0];
    const float* Wm   = (const float*)d_in[1];
    const float* U    = (const float*)d_in[2];
    const float* bias = (const float*)d_in[3];
    float* out = (float*)d_out;
    (void)in_sizes; (void)n_in;

    const int smem_rec = SMEM_ELEMS * (int)sizeof(float);   // 44032 B
    cudaFuncSetAttribute(lstm_rec, cudaFuncAttributeMaxDynamicSharedMemorySize, smem_rec);

    const long long need_hc = (long long)B_ * T_ * HS_ + 2LL * B_ * HS_;
    int write_hc = ((long long)out_size >= need_hc) ? 1 : 0;

    prep_all<<<17952, 256>>>(x, Wm, U);
    xw_mma<<<dim3(16, 1024), 256>>>(bias);
    lstm_rec<<<RCTA, RTHR, smem_rec>>>(out, write_hc);
}

// round 14
// speedup vs baseline: 1.4034x; 1.0408x over previous
#include <cuda_runtime.h>
#include <cuda_bf16.h>
#include <cstdint>

#define B_   128
#define T_   1024
#define D_   256
#define HS_  512
#define G4_  2048
#define M1_  (B_ * T_)

#define RCTA 128
#define RTHR 512

// ---------------- device scratch ----------------
__device__ float g_xw[(size_t)M1_ * G4_];            // [(row*T+t)*2048 + pc]
__device__ uint4 g_uf[64 * 32 * 4 * 32];             // U frags [cg][kt][nt][lane]
__device__ uint4 g_xfh[(size_t)8192 * 16 * 32];      // x A-frags hi
__device__ uint4 g_xfl[(size_t)8192 * 16 * 32];      // x A-frags lo
__device__ uint4 g_wf[16 * 16 * 16 * 32];            // W B-frags
__device__ uint4 g_hfh[2][8 * 32 * 32];              // h hi A-frags
__device__ uint4 g_hfl[2][8 * 32 * 32];              // h lo A-frags
__device__ unsigned int g_bar_l1[16 * 32];           // tree barrier leaves (128B stride)
__device__ unsigned int g_bar_l2;                    // tree barrier root
__device__ unsigned int g_bar_epoch;

// ---------------- helpers ----------------
__device__ __forceinline__ uint32_t packbf(__nv_bfloat16 a, __nv_bfloat16 b) {
    return ((uint32_t)(*(uint16_t*)&b) << 16) | (uint32_t)(*(uint16_t*)&a);
}
__device__ __forceinline__ void split2(float a, float b, uint32_t& hi, uint32_t& lo) {
    __nv_bfloat16 ah = __float2bfloat16(a), bh = __float2bfloat16(b);
    __nv_bfloat16 al = __float2bfloat16(a - __bfloat162float(ah));
    __nv_bfloat16 bl = __float2bfloat16(b - __bfloat162float(bh));
    hi = packbf(ah, bh);
    lo = packbf(al, bl);
}
__device__ __forceinline__ void mma16816(float* d, const uint4& a, uint32_t b0, uint32_t b1) {
    asm volatile(
        "mma.sync.aligned.m16n8k16.row.col.f32.bf16.bf16.f32 "
        "{%0,%1,%2,%3}, {%4,%5,%6,%7}, {%8,%9}, {%0,%1,%2,%3};"
        : "+f"(d[0]), "+f"(d[1]), "+f"(d[2]), "+f"(d[3])
        : "r"(a.x), "r"(a.y), "r"(a.z), "r"(a.w), "r"(b0), "r"(b1));
}
__device__ __forceinline__ unsigned atom_add_release(unsigned* p, unsigned v) {
    unsigned old;
    asm volatile("atom.release.gpu.global.add.u32 %0, [%1], %2;"
                 : "=r"(old) : "l"(p), "r"(v) : "memory");
    return old;
}
__device__ __forceinline__ void st_release(unsigned* p, unsigned v) {
    asm volatile("st.release.gpu.global.u32 [%0], %1;" :: "l"(p), "r"(v) : "memory");
}
__device__ __forceinline__ unsigned ld_acquire(const unsigned* p) {
    unsigned v;
    asm volatile("ld.acquire.gpu.global.u32 %0, [%1];" : "=r"(v) : "l"(p) : "memory");
    return v;
}
__device__ __forceinline__ float sigmoid_fast(float x) { return 1.f / (1.f + __expf(-x)); }
__device__ __forceinline__ float tanh_fast(float x) { float e = __expf(2.f * x); return 1.f - 2.f / (e + 1.f); }

// orig gate col c = gate*512 + hcol -> pc = (hcol/8)*32 + gate*8 + hcol%8
__device__ __forceinline__ int cperm(int c) {
    int g = c >> 9, hc = c & 511;
    return ((hc >> 3) << 5) + (g << 3) + (hc & 7);
}

// ---------------- merged prep: split_xf | wf | uf | init ----------------
__global__ __launch_bounds__(256) void prep_all(const float* __restrict__ x,
                                                const float* __restrict__ Wm,
                                                const float* __restrict__ U) {
    const int bid = blockIdx.x;
    const int tid = threadIdx.x;
    if (bid < 16384) {
        size_t i = (size_t)bid * 256 + tid;
        int l = (int)(i & 31), kt = (int)((i >> 5) & 15);
        int rg = (int)(i >> 9);
        int row = rg * 16 + (l >> 2);
        int k0 = kt * 16 + (l & 3) * 2;
        uint32_t hi[4], lo[4];
#pragma unroll
        for (int kh = 0; kh < 2; kh++)
#pragma unroll
            for (int rh = 0; rh < 2; rh++) {
                float2 v = *(const float2*)&x[(size_t)(row + 8 * rh) * D_ + k0 + 8 * kh];
                split2(v.x, v.y, hi[kh * 2 + rh], lo[kh * 2 + rh]);
            }
        g_xfh[i] = make_uint4(hi[0], hi[1], hi[2], hi[3]);
        g_xfl[i] = make_uint4(lo[0], lo[1], lo[2], lo[3]);
    } else if (bid < 16896) {
        int i = (bid - 16384) * 256 + tid;
        int l = i & 31, nc = (i >> 5) & 15, kt = (i >> 9) & 15, cb = i >> 13;
        int n = cb * 128 + nc * 8 + (l >> 2);
        int k0 = kt * 16 + (l & 3) * 2;
        float u00 = Wm[(size_t)k0 * G4_ + n];
        float u01 = Wm[(size_t)(k0 + 1) * G4_ + n];
        float u10 = Wm[(size_t)(k0 + 8) * G4_ + n];
        float u11 = Wm[(size_t)(k0 + 9) * G4_ + n];
        uint32_t b0h, b0l, b1h, b1l;
        split2(u00, u01, b0h, b0l);
        split2(u10, u11, b1h, b1l);
        g_wf[i] = make_uint4(b0h, b1h, b0l, b1l);
    } else if (bid < 17920) {
        int i = (bid - 16896) * 256 + tid;
        int l = i & 31, nt = (i >> 5) & 3, kt = (i >> 7) & 31, cg = i >> 12;
        int n = nt * 8 + (l >> 2);
        int k0 = kt * 16 + (l & 3) * 2;
        int c = (n >> 3) * 512 + cg * 8 + (n & 7);
        float u00 = U[(size_t)k0 * G4_ + c];
        float u01 = U[(size_t)(k0 + 1) * G4_ + c];
        float u10 = U[(size_t)(k0 + 8) * G4_ + c];
        float u11 = U[(size_t)(k0 + 9) * G4_ + c];
        uint32_t b0h, b0l, b1h, b1l;
        split2(u00, u01, b0h, b0l);
        split2(u10, u11, b1h, b1l);
        g_uf[i] = make_uint4(b0h, b1h, b0l, b1l);
    } else {
        int i = (bid - 17920) * 256 + tid;           // 0..8191
        if (i == 0) { g_bar_l2 = 0; g_bar_epoch = 0; }
        if (i < 16 * 32) g_bar_l1[i] = 0u;
        g_hfh[0][i] = make_uint4(0, 0, 0, 0);
        g_hfl[0][i] = make_uint4(0, 0, 0, 0);
    }
}

// ---------------- phase 1: xW = x @ W + bias (mma.sync) ----------------
__global__ __launch_bounds__(256) void xw_mma(const float* __restrict__ bias) {
    const int tid = threadIdx.x;
    const int w = tid >> 5, l = tid & 31;
    const int cb = blockIdx.x, rb = blockIdx.y;
    const int wr = w & 3, wc = w >> 2;

    float acc[2][8][4];
#pragma unroll
    for (int mt = 0; mt < 2; mt++)
#pragma unroll
        for (int nt = 0; nt < 8; nt++)
#pragma unroll
            for (int q = 0; q < 4; q++) acc[mt][nt][q] = 0.f;

#pragma unroll 4
    for (int kt = 0; kt < 16; kt++) {
        uint4 bf[8];
#pragma unroll
        for (int nt = 0; nt < 8; nt++)
            bf[nt] = __ldg(&g_wf[(((cb * 16 + kt) * 16) + wc * 8 + nt) * 32 + l]);
#pragma unroll
        for (int mt = 0; mt < 2; mt++) {
            size_t rg = (size_t)rb * 8 + wr * 2 + mt;
            uint4 ah = __ldg(&g_xfh[(rg * 16 + kt) * 32 + l]);
            uint4 al = __ldg(&g_xfl[(rg * 16 + kt) * 32 + l]);
#pragma unroll
            for (int nt = 0; nt < 8; nt++) {
                mma16816(acc[mt][nt], ah, bf[nt].x, bf[nt].y);
                mma16816(acc[mt][nt], ah, bf[nt].z, bf[nt].w);
                mma16816(acc[mt][nt], al, bf[nt].x, bf[nt].y);
            }
        }
    }

#pragma unroll
    for (int mt = 0; mt < 2; mt++) {
        int r0 = rb * 128 + wr * 32 + mt * 16 + (l >> 2);
#pragma unroll
        for (int nt = 0; nt < 8; nt++) {
            int c = cb * 128 + wc * 64 + nt * 8 + (l & 3) * 2;
            int pc = cperm(c);
            float2 bv = __ldg((const float2*)&bias[c]);
            *(float2*)&g_xw[(size_t)r0 * G4_ + pc] =
                make_float2(acc[mt][nt][0] + bv.x, acc[mt][nt][1] + bv.y);
            *(float2*)&g_xw[(size_t)(r0 + 8) * G4_ + pc] =
                make_float2(acc[mt][nt][2] + bv.x, acc[mt][nt][3] + bv.y);
        }
    }
}

// ---------------- phase 2: persistent mma.sync recurrence ----------------
// 128 CTAs x 512 thr. cta = cg*2 + mh: cg owns 8 hcols (32 pc), mh owns row half.
// Warp (mq=w>>2, kq=w&3): M=16 (1 mt), N=32 (4 nt), K=128 (8 kt).
// Disjoint A slices per warp -> no redundant A L2 traffic.
#define SPAD  34
#define XPAD  36
#define SRED_ELEMS (4 * 64 * SPAD)
#define SMEM_ELEMS (SRED_ELEMS + 64 * XPAD)

__global__ __launch_bounds__(RTHR, 1) void lstm_rec(float* __restrict__ out,
                                                    int write_hc) {
    extern __shared__ float smemf[];
    float* sred = smemf;
    float* xw_s = smemf + SRED_ELEMS;

    const int tid = threadIdx.x;
    const int w = tid >> 5, l = tid & 31;
    const int cta = blockIdx.x;
    const int cg = cta >> 1, mh = cta & 1;
    const int mq = w >> 2, kq = w & 3;

    // epilogue role (tid < 256): 2 cells = row x hcols {2hp, 2hp+1}
    const int rl = (tid & 255) >> 2, hp = tid & 3;
    const int row_g = mh * 64 + rl;
    const size_t fragidx = ((size_t)(row_g >> 4) * 32 + (cg >> 1)) * 32 + (row_g & 7) * 4 + hp;
    const int regb = (cg & 1) * 2 + ((row_g >> 3) & 1);

    const uint4* __restrict__ ub = g_uf + (size_t)cg * 4096;

    const int xw_rwl = tid >> 3;                     // local row 0..63
    const int xw_co  = cg * 32 + (tid & 7) * 4;
    // A slot: global 16-row group = mh*4 + mq; + kt*32 + l
    const int aslot_base = ((mh * 4 + mq) * 32) * 32 + l;

    float creg[2] = {0.f, 0.f};
    float hlast[2];

    // xw prefetch for t = 0
    float4 xr = __ldcg((const float4*)&g_xw[((size_t)(mh * 64 + xw_rwl) * T_ + 0) * G4_ + xw_co]);

    for (int t = 0; t < T_; t++) {
        const int p = t & 1;
        const uint4* __restrict__ Ah = g_hfh[p];
        const uint4* __restrict__ Al = g_hfl[p];

        float acc[4][4];
#pragma unroll
        for (int nt = 0; nt < 4; nt++)
#pragma unroll
            for (int q = 0; q < 4; q++) acc[nt][q] = 0.f;

        // ---- mainloop: kt = kq*8 + i, double-buffered A (1 mt) ----
        uint4 ahb[2], alb[2];
        {
            const int slot = aslot_base + (kq * 8) * 32;
            ahb[0] = __ldcg(&Ah[slot]);
            alb[0] = __ldcg(&Al[slot]);
        }
#pragma unroll
        for (int i = 0; i < 8; i++) {
            const int cur = i & 1;
            if (i < 7) {
                const int slot = aslot_base + (kq * 8 + i + 1) * 32;
                ahb[cur ^ 1] = __ldcg(&Ah[slot]);
                alb[cur ^ 1] = __ldcg(&Al[slot]);
            }
            const int kt = kq * 8 + i;
            uint4 bf[4];
#pragma unroll
            for (int nt = 0; nt < 4; nt++)
                bf[nt] = __ldg(&ub[(kt * 4 + nt) * 32 + l]);
#pragma unroll
            for (int nt = 0; nt < 4; nt++) {
                mma16816(acc[nt], ahb[cur], bf[nt].x, bf[nt].y);
                mma16816(acc[nt], ahb[cur], bf[nt].z, bf[nt].w);
                mma16816(acc[nt], alb[cur], bf[nt].x, bf[nt].y);
            }
        }

        // ---- partials + xw to smem ----
        {
            const int row0 = (l >> 2), n0 = 2 * (l & 3);
#pragma unroll
            for (int nt = 0; nt < 4; nt++) {
                int s = (kq * 64 + mq * 16 + row0) * SPAD + nt * 8 + n0;
                *(float2*)&sred[s]            = make_float2(acc[nt][0], acc[nt][1]);
                *(float2*)&sred[s + 8 * SPAD] = make_float2(acc[nt][2], acc[nt][3]);
            }
            *(float4*)&xw_s[xw_rwl * XPAD + (tid & 7) * 4] = xr;
        }
        __syncthreads();

        // ---- reduce + cell update (tid < 256) ----
        float hnew[2];
        if (tid < 256) {
            float2 gsum[4];
#pragma unroll
            for (int g = 0; g < 4; g++) {
                float2 s = *(const float2*)&xw_s[rl * XPAD + g * 8 + 2 * hp];
#pragma unroll
                for (int q2 = 0; q2 < 4; q2++) {
                    float2 v = *(const float2*)&sred[(q2 * 64 + rl) * SPAD + g * 8 + 2 * hp];
                    s.x += v.x; s.y += v.y;
                }
                gsum[g] = s;
            }
#pragma unroll
            for (int q = 0; q < 2; q++) {
                float gi = q ? gsum[0].y : gsum[0].x;
                float gf = q ? gsum[1].y : gsum[1].x;
                float gg = q ? gsum[2].y : gsum[2].x;
                float go = q ? gsum[3].y : gsum[3].x;
                float iv = sigmoid_fast(gi);
                float fv = sigmoid_fast(gf);
                float gv = tanh_fast(gg);
                float ov = sigmoid_fast(go);
                float c = fv * creg[q] + iv * gv;
                creg[q] = c;
                float h = ov * tanh_fast(c);
                hnew[q] = h;
                hlast[q] = h;
            }
            // h fragment write for next step (before barrier arrival)
            uint32_t hi, lo;
            split2(hnew[0], hnew[1], hi, lo);
            *(uint32_t*)((char*)g_hfh[1 - p] + fragidx * 16 + regb * 4) = hi;
            *(uint32_t*)((char*)g_hfl[1 - p] + fragidx * 16 + regb * 4) = lo;
        }

        if (t < T_ - 1) {
            const unsigned tgt = (unsigned)(t + 1);
            __syncthreads();   // all h stores precede tid0's release-arrive
            if (tid == 0) {
                unsigned old = atom_add_release(&g_bar_l1[(cta & 15) * 32], 1u);
                if (old == 8u * tgt - 1u) {
                    unsigned old2 = atom_add_release(&g_bar_l2, 1u);
                    if (old2 == 16u * tgt - 1u)
                        st_release(&g_bar_epoch, tgt);
                }
            }
            // overlap with the barrier: out store + next-step xw prefetch
            if (tid < 256)
                *(float2*)&out[((size_t)row_g * T_ + t) * HS_ + cg * 8 + 2 * hp] =
                    make_float2(hnew[0], hnew[1]);
            xr = __ldcg((const float4*)&g_xw[((size_t)(mh * 64 + xw_rwl) * T_ + (t + 1)) * G4_ + xw_co]);
            if (tid == 0) {
                while (ld_acquire(&g_bar_epoch) < tgt) { }
            }
            __syncthreads();
        } else {
            if (tid < 256)
                *(float2*)&out[((size_t)row_g * T_ + t) * HS_ + cg * 8 + 2 * hp] =
                    make_float2(hnew[0], hnew[1]);
        }
    }

    if (write_hc && tid < 256) {
        const size_t OH = (size_t)B_ * T_ * HS_;
        *(float2*)&out[OH + (size_t)row_g * HS_ + cg * 8 + 2 * hp] =
            make_float2(hlast[0], hlast[1]);
        *(float2*)&out[OH + (size_t)B_ * HS_ + (size_t)row_g * HS_ + cg * 8 + 2 * hp] =
            make_float2(creg[0], creg[1]);
    }
}

// ---------------- launch ----------------
extern "C" void kernel_launch(void* const* d_in, const int* in_sizes, int n_in,
                              void* d_out, int out_size) {
    const float* x    = (const float*)d_in[0];
    const float* Wm   = (const float*)d_in[1];
    const float* U    = (const float*)d_in[2];
    const float* bias = (const float*)d_in[3];
    float* out = (float*)d_out;
    (void)in_sizes; (void)n_in;

    const int smem_rec = SMEM_ELEMS * (int)sizeof(float);   // 44032 B
    cudaFuncSetAttribute(lstm_rec, cudaFuncAttributeMaxDynamicSharedMemorySize, smem_rec);

    const long long need_hc = (long long)B_ * T_ * HS_ + 2LL * B_ * HS_;
    int write_hc = ((long long)out_size >= need_hc) ? 1 : 0;

    prep_all<<<17952, 256>>>(x, Wm, U);
    xw_mma<<<dim3(16, 1024), 256>>>(bias);
    lstm_rec<<<RCTA, RTHR, smem_rec>>>(out, write_hc);
}